// round 1
// baseline (speedup 1.0000x reference)
#include <cuda_runtime.h>
#include <cuda_bf16.h>

#define NN 50000
#define EE 500000
#define ET (EE + NN)          // edges incl. self loops
#define DD 256
#define HH 8
#define HDIM 32
#define NEGS 0.2f

// ---------------- scratch (static device memory, no allocs) ----------------
__device__ float    g_x[NN * DD];        // current activations / aggregation accumulator
__device__ float    g_h[NN * DD];        // h = x @ W
__device__ float    g_el[NN * HH];
__device__ float    g_er[NN * HH];
__device__ unsigned g_menc[NN * HH];     // encoded segment max
__device__ float    g_z[NN * HH];        // softmax denominators
__device__ float    g_a[ET * HH];        // exp(e - m) per edge-head

// ---------------- helpers ----------------
__device__ __forceinline__ float leaky(float v) { return v > 0.f ? v : NEGS * v; }

// monotonic float<->uint mapping so unsigned atomicMax == float max
__device__ __forceinline__ unsigned fenc(float f) {
    unsigned u = __float_as_uint(f);
    return (u & 0x80000000u) ? ~u : (u | 0x80000000u);
}
__device__ __forceinline__ float fdec(unsigned u) {
    u = (u & 0x80000000u) ? (u & 0x7fffffffu) : ~u;
    return __uint_as_float(u);
}

// ---------------- tiled SGEMM: C[M,256] = A[M,256] @ B[256,256] (+bias) ----------------
#define BM 64
#define BN 64
#define BK 16
#define TM 4
#define TN 4

__global__ void sgemm_bias(const float* __restrict__ A, const float* __restrict__ B,
                           const float* __restrict__ bias, float* __restrict__ C, int M) {
    __shared__ float As[BK][BM + 1];
    __shared__ float Bs[BK][BN + 1];
    const int bc = blockIdx.x, br = blockIdx.y;
    const int tx = threadIdx.x & 15, ty = threadIdx.x >> 4;
    const int row0 = br * BM, col0 = bc * BN;
    float acc[TM][TN] = {};

    for (int k0 = 0; k0 < DD; k0 += BK) {
        #pragma unroll
        for (int i = threadIdx.x; i < BM * BK; i += 256) {
            int r = i / BK, c = i % BK;
            int gr = row0 + r;
            As[c][r] = (gr < M) ? A[gr * DD + k0 + c] : 0.f;
        }
        #pragma unroll
        for (int i = threadIdx.x; i < BK * BN; i += 256) {
            int r = i / BN, c = i % BN;
            Bs[r][c] = B[(k0 + r) * DD + col0 + c];
        }
        __syncthreads();
        #pragma unroll
        for (int k = 0; k < BK; k++) {
            float a[TM], b[TN];
            #pragma unroll
            for (int i = 0; i < TM; i++) a[i] = As[k][ty * TM + i];
            #pragma unroll
            for (int j = 0; j < TN; j++) b[j] = Bs[k][tx * TN + j];
            #pragma unroll
            for (int i = 0; i < TM; i++)
                #pragma unroll
                for (int j = 0; j < TN; j++) acc[i][j] += a[i] * b[j];
        }
        __syncthreads();
    }
    #pragma unroll
    for (int i = 0; i < TM; i++) {
        int gr = row0 + ty * TM + i;
        if (gr >= M) continue;
        #pragma unroll
        for (int j = 0; j < TN; j++) {
            int gc = col0 + tx * TN + j;
            float v = acc[i][j];
            if (bias) v += bias[gc];
            C[gr * DD + gc] = v;
        }
    }
}

// ---------------- el/er: per-node per-head dot(h, al/ar) ----------------
__global__ void node_attn(const float* __restrict__ h, const float* __restrict__ al,
                          const float* __restrict__ ar, float* __restrict__ el,
                          float* __restrict__ er) {
    int n = blockIdx.x;
    int head = threadIdx.x >> 5, lane = threadIdx.x & 31;
    float v = h[n * DD + head * HDIM + lane];
    float sl = v * al[head * HDIM + lane];
    float sr = v * ar[head * HDIM + lane];
    #pragma unroll
    for (int o = 16; o; o >>= 1) {
        sl += __shfl_down_sync(0xffffffffu, sl, o);
        sr += __shfl_down_sync(0xffffffffu, sr, o);
    }
    if (lane == 0) {
        el[n * HH + head] = sl;
        er[n * HH + head] = sr;
    }
}

// ---------------- zero accumulators ----------------
__global__ void zero_init(float* __restrict__ acc, unsigned* __restrict__ menc,
                          float* __restrict__ z) {
    int i = blockIdx.x * blockDim.x + threadIdx.x;
    if (i < NN * DD) acc[i] = 0.f;
    if (i < NN * HH) { menc[i] = 0u; z[i] = 0.f; }
}

// ---------------- edge pass 1: segment max of leaky(el[s]+er[d]) ----------------
__global__ void edge_pass1(const int* __restrict__ src, const int* __restrict__ dst,
                           const float* __restrict__ el, const float* __restrict__ er,
                           unsigned* __restrict__ menc) {
    int i = blockIdx.x * blockDim.x + threadIdx.x;
    if (i >= ET) return;
    int s = (i < EE) ? src[i] : (i - EE);
    int d = (i < EE) ? dst[i] : (i - EE);
    float lv[8], rv[8];
    ((float4*)lv)[0] = ((const float4*)(el + s * HH))[0];
    ((float4*)lv)[1] = ((const float4*)(el + s * HH))[1];
    ((float4*)rv)[0] = ((const float4*)(er + d * HH))[0];
    ((float4*)rv)[1] = ((const float4*)(er + d * HH))[1];
    #pragma unroll
    for (int hh = 0; hh < HH; hh++) {
        float e = leaky(lv[hh] + rv[hh]);
        atomicMax(&menc[d * HH + hh], fenc(e));
    }
}

// ---------------- edge pass 2: a = exp(e - m), z += a ----------------
__global__ void edge_pass2(const int* __restrict__ src, const int* __restrict__ dst,
                           const float* __restrict__ el, const float* __restrict__ er,
                           const unsigned* __restrict__ menc, float* __restrict__ z,
                           float* __restrict__ a) {
    int i = blockIdx.x * blockDim.x + threadIdx.x;
    if (i >= ET) return;
    int s = (i < EE) ? src[i] : (i - EE);
    int d = (i < EE) ? dst[i] : (i - EE);
    float lv[8], rv[8];
    unsigned mv[8];
    ((float4*)lv)[0] = ((const float4*)(el + s * HH))[0];
    ((float4*)lv)[1] = ((const float4*)(el + s * HH))[1];
    ((float4*)rv)[0] = ((const float4*)(er + d * HH))[0];
    ((float4*)rv)[1] = ((const float4*)(er + d * HH))[1];
    ((uint4*)mv)[0] = ((const uint4*)(menc + d * HH))[0];
    ((uint4*)mv)[1] = ((const uint4*)(menc + d * HH))[1];
    #pragma unroll
    for (int hh = 0; hh < HH; hh++) {
        float e = leaky(lv[hh] + rv[hh]);
        float av = __expf(e - fdec(mv[hh]));
        a[(long)i * HH + hh] = av;
        atomicAdd(&z[d * HH + hh], av);
    }
}

// ---------------- edge pass 3: out[dst] += (a/z[dst]) * h[src], warp per edge ----------------
__global__ void edge_agg(const int* __restrict__ src, const int* __restrict__ dst,
                         const float* __restrict__ a, const float* __restrict__ z,
                         const float* __restrict__ h, float* __restrict__ out) {
    int gt = blockIdx.x * blockDim.x + threadIdx.x;
    int w = gt >> 5, lane = gt & 31;
    if (w >= ET) return;
    int s = (w < EE) ? __ldg(src + w) : (w - EE);
    int d = (w < EE) ? __ldg(dst + w) : (w - EE);
    int head = lane >> 2;                    // lane covers 8 consecutive cols, 4 lanes/head
    float alpha = a[(long)w * HH + head] / z[d * HH + head];
    const float4* hp = (const float4*)(h + s * DD + lane * 8);
    float4 v0 = hp[0], v1 = hp[1];
    v0.x *= alpha; v0.y *= alpha; v0.z *= alpha; v0.w *= alpha;
    v1.x *= alpha; v1.y *= alpha; v1.z *= alpha; v1.w *= alpha;
    float* op = out + d * DD + lane * 8;
    asm volatile("red.global.add.v4.f32 [%0], {%1,%2,%3,%4};"
                 :: "l"(op), "f"(v0.x), "f"(v0.y), "f"(v0.z), "f"(v0.w) : "memory");
    asm volatile("red.global.add.v4.f32 [%0], {%1,%2,%3,%4};"
                 :: "l"(op + 4), "f"(v1.x), "f"(v1.y), "f"(v1.z), "f"(v1.w) : "memory");
}

// ---------------- bias + leaky relu ----------------
__global__ void bias_act(const float* __restrict__ in, const float* __restrict__ b,
                         float* __restrict__ o) {
    int i = blockIdx.x * blockDim.x + threadIdx.x;
    if (i >= NN * DD) return;
    float v = in[i] + b[i & (DD - 1)];
    o[i] = v > 0.f ? v : NEGS * v;
}

// ---------------- driver ----------------
extern "C" void kernel_launch(void* const* d_in, const int* in_sizes, int n_in,
                              void* d_out, int out_size) {
    const float* feats  = (const float*)d_in[0];
    const int*   src    = (const int*)d_in[1];
    const int*   dst    = (const int*)d_in[2];
    const float* proj_W = (const float*)d_in[3];
    const float* proj_b = (const float*)d_in[4];
    const float* Ws[2]  = { (const float*)d_in[5], (const float*)d_in[9] };
    const float* als[2] = { (const float*)d_in[6], (const float*)d_in[10] };
    const float* ars[2] = { (const float*)d_in[7], (const float*)d_in[11] };
    const float* bs[2]  = { (const float*)d_in[8], (const float*)d_in[12] };
    float* out = (float*)d_out;

    float *x, *h, *el, *er, *z, *a;
    unsigned* menc;
    cudaGetSymbolAddress((void**)&x, g_x);
    cudaGetSymbolAddress((void**)&h, g_h);
    cudaGetSymbolAddress((void**)&el, g_el);
    cudaGetSymbolAddress((void**)&er, g_er);
    cudaGetSymbolAddress((void**)&menc, g_menc);
    cudaGetSymbolAddress((void**)&z, g_z);
    cudaGetSymbolAddress((void**)&a, g_a);

    dim3 ggrid(DD / BN, (NN + BM - 1) / BM);

    // projection: x = feats @ proj_W + proj_b
    sgemm_bias<<<ggrid, 256>>>(feats, proj_W, proj_b, x, NN);

    for (int layer = 0; layer < 2; layer++) {
        // h = x @ W
        sgemm_bias<<<ggrid, 256>>>(x, Ws[layer], nullptr, h, NN);
        // el/er
        node_attn<<<NN, 256>>>(h, als[layer], ars[layer], el, er);
        // zero accumulator (x is dead after GEMM), max, z
        zero_init<<<(NN * DD + 255) / 256, 256>>>(x, menc, z);
        // softmax over destination neighborhoods
        edge_pass1<<<(ET + 255) / 256, 256>>>(src, dst, el, er, menc);
        edge_pass2<<<(ET + 255) / 256, 256>>>(src, dst, el, er, menc, z, a);
        // weighted aggregation: warp per edge
        long tthreads = (long)ET * 32;
        edge_agg<<<(unsigned)((tthreads + 255) / 256), 256>>>(src, dst, a, z, h, x);
        // bias + module leaky
        float* dbuf = (layer == 1) ? out : x;
        bias_act<<<(NN * DD + 255) / 256, 256>>>(x, bs[layer], dbuf);
    }
}

// round 3
// speedup vs baseline: 2.0664x; 2.0664x over previous
#include <cuda_runtime.h>
#include <cuda_bf16.h>
#include <cstdint>

#define NN 50000
#define EE 500000
#define ET (EE + NN)
#define DD 256
#define HH 8
#define NEGS 0.2f

#define KS 512                  // stored split-K: [0,256)=hi, [256,512)=lo
#define BM 128
#define BN 128
#define NCHUNK 12               // 3 passes x 4 chunks of K=64
#define NTILES ((NN + BM - 1) / BM)   // 391
#define MPAD (NTILES * BM)            // 50048

// ---------------- scratch ----------------
__device__ __nv_bfloat16 g_A[(size_t)MPAD * KS];   // split activations (pad rows stay 0)
__device__ __nv_bfloat16 g_B[(size_t)DD * KS];     // split weight, B^T layout [n][k]
__device__ float g_x[NN * DD];
__device__ float g_h[NN * DD];
__device__ float g_el[NN * HH];
__device__ float g_er[NN * HH];
__device__ float g_z[NN * HH];

__device__ __forceinline__ float leaky(float v) { return v > 0.f ? v : NEGS * v; }
__device__ __forceinline__ uint32_t smem_u32(const void* p) {
    return (uint32_t)__cvta_generic_to_shared(p);
}

// ---------------- split kernels (fp32 -> bf16 hi/lo) ----------------
__global__ void split_act(const float* __restrict__ x, __nv_bfloat16* __restrict__ A) {
    int i = blockIdx.x * blockDim.x + threadIdx.x;
    if (i >= NN * DD) return;
    int m = i >> 8, c = i & 255;
    float v = x[i];
    __nv_bfloat16 hi = __float2bfloat16(v);
    float lo = v - __bfloat162float(hi);
    A[(size_t)m * KS + c] = hi;
    A[(size_t)m * KS + 256 + c] = __float2bfloat16(lo);
}
__global__ void split_w(const float* __restrict__ W, __nv_bfloat16* __restrict__ Bm) {
    int i = blockIdx.x * blockDim.x + threadIdx.x;
    if (i >= DD * DD) return;
    int k = i >> 8, n = i & 255;           // W[k][n]
    float v = W[i];
    __nv_bfloat16 hi = __float2bfloat16(v);
    float lo = v - __bfloat162float(hi);
    Bm[(size_t)n * KS + k] = hi;
    Bm[(size_t)n * KS + 256 + k] = __float2bfloat16(lo);
}

// ---------------- HMMA GEMM ----------------
// SMEM per stage: A 128x64 bf16 (16KB) + B 128x64 bf16 (16KB); 2 stages = 64KB.
// 16B-unit swizzle: unit s (0..7) at row r stored at column s^(r&7).
#define STG 32768

__device__ __forceinline__ void fill_stage(const __nv_bfloat16* A, const __nv_bfloat16* B,
                                           uint32_t aB, uint32_t bB,
                                           int m0, int n0, int c, int tid) {
    int p = c >> 2, j = c & 3;
    int kA = ((p == 1) ? 256 : 0) + j * 64;
    int kB = ((p == 2) ? 256 : 0) + j * 64;
    const char* Ag = (const char*)(A + (size_t)m0 * KS + kA);
    const char* Bg = (const char*)(B + (size_t)n0 * KS + kB);
    #pragma unroll
    for (int i = 0; i < 4; i++) {
        int u = tid + i * 256;
        int r = u >> 3, s = u & 7;
        uint32_t off = (uint32_t)r * 128 + (uint32_t)((s ^ (r & 7)) << 4);
        unsigned long long sa = __cvta_generic_to_global(Ag + (size_t)r * 1024 + s * 16);
        unsigned long long sbg = __cvta_generic_to_global(Bg + (size_t)r * 1024 + s * 16);
        asm volatile("cp.async.cg.shared.global [%0], [%1], 16;" :: "r"(aB + off), "l"(sa));
        asm volatile("cp.async.cg.shared.global [%0], [%1], 16;" :: "r"(bB + off), "l"(sbg));
    }
}

__device__ __forceinline__ void mma16816(float* d, const uint32_t* a, const uint32_t* b) {
    asm volatile("mma.sync.aligned.m16n8k16.row.col.f32.bf16.bf16.f32 "
                 "{%0,%1,%2,%3}, {%4,%5,%6,%7}, {%8,%9}, {%0,%1,%2,%3};"
                 : "+f"(d[0]), "+f"(d[1]), "+f"(d[2]), "+f"(d[3])
                 : "r"(a[0]), "r"(a[1]), "r"(a[2]), "r"(a[3]), "r"(b[0]), "r"(b[1]));
}

__global__ void __launch_bounds__(256)
gemm_bf16x3(const __nv_bfloat16* __restrict__ A, const __nv_bfloat16* __restrict__ B,
            const float* __restrict__ bias, float* __restrict__ out) {
    extern __shared__ char smem[];
    uint32_t sb = smem_u32(smem);
    int tid = threadIdx.x, wid = tid >> 5, lane = tid & 31;
    int m0 = blockIdx.y * BM, n0 = blockIdx.x * BN;
    int warp_m = (wid & 3) * 32, warp_n = (wid >> 2) * 64;

    float acc[2][8][4];
    #pragma unroll
    for (int mt = 0; mt < 2; mt++)
        #pragma unroll
        for (int nt = 0; nt < 8; nt++)
            #pragma unroll
            for (int q = 0; q < 4; q++) acc[mt][nt][q] = 0.f;

    fill_stage(A, B, sb, sb + 16384, m0, n0, 0, tid);
    asm volatile("cp.async.commit_group;" ::: "memory");

    for (int c = 0; c < NCHUNK; c++) {
        if (c + 1 < NCHUNK) {
            uint32_t st = ((c + 1) & 1) * STG;
            fill_stage(A, B, sb + st, sb + st + 16384, m0, n0, c + 1, tid);
            asm volatile("cp.async.commit_group;" ::: "memory");
            asm volatile("cp.async.wait_group 1;" ::: "memory");
        } else {
            asm volatile("cp.async.wait_group 0;" ::: "memory");
        }
        __syncthreads();
        uint32_t as = sb + (c & 1) * STG;
        uint32_t bs = as + 16384;
        #pragma unroll
        for (int kk = 0; kk < 4; kk++) {
            uint32_t a[2][4], b[8][2];
            // A frags: lanes 0-7 rows0-7/kh0, 8-15 rows8-15/kh0, 16-23 rows0-7/kh1, 24-31 rows8-15/kh1
            {
                int rr = lane & 15, half = lane >> 4;
                int s = kk * 2 + half;
                #pragma unroll
                for (int mt = 0; mt < 2; mt++) {
                    int row = warp_m + mt * 16 + rr;
                    uint32_t ad = as + (uint32_t)row * 128 + (uint32_t)((s ^ (row & 7)) << 4);
                    asm volatile("ldmatrix.sync.aligned.m8n8.x4.shared.b16 {%0,%1,%2,%3}, [%4];"
                                 : "=r"(a[mt][0]), "=r"(a[mt][1]), "=r"(a[mt][2]), "=r"(a[mt][3])
                                 : "r"(ad));
                }
            }
            // B frags: each x4 covers 2 n8 tiles
            {
                int half = (lane >> 3) & 1;
                int s = kk * 2 + half;
                int nro = ((lane >> 4) << 3) + (lane & 7);
                #pragma unroll
                for (int j = 0; j < 4; j++) {
                    int row = warp_n + j * 16 + nro;
                    uint32_t bd = bs + (uint32_t)row * 128 + (uint32_t)((s ^ (row & 7)) << 4);
                    asm volatile("ldmatrix.sync.aligned.m8n8.x4.shared.b16 {%0,%1,%2,%3}, [%4];"
                                 : "=r"(b[2*j][0]), "=r"(b[2*j][1]), "=r"(b[2*j+1][0]), "=r"(b[2*j+1][1])
                                 : "r"(bd));
                }
            }
            #pragma unroll
            for (int mt = 0; mt < 2; mt++)
                #pragma unroll
                for (int nt = 0; nt < 8; nt++)
                    mma16816(acc[mt][nt], a[mt], b[nt]);
        }
        __syncthreads();
    }

    // epilogue: thread holds rows lane/4 (+8), cols (lane%4)*2 (+1) per n8 tile
    int rin = lane >> 2, colq = (lane & 3) * 2;
    #pragma unroll
    for (int mt = 0; mt < 2; mt++) {
        int r0 = m0 + warp_m + mt * 16 + rin;
        #pragma unroll
        for (int nt = 0; nt < 8; nt++) {
            int cb = n0 + warp_n + nt * 8 + colq;
            float b0 = bias ? bias[cb] : 0.f, b1 = bias ? bias[cb + 1] : 0.f;
            if (r0 < NN) {
                float2 v = make_float2(acc[mt][nt][0] + b0, acc[mt][nt][1] + b1);
                *(float2*)(out + (size_t)r0 * DD + cb) = v;
            }
            if (r0 + 8 < NN) {
                float2 v = make_float2(acc[mt][nt][2] + b0, acc[mt][nt][3] + b1);
                *(float2*)(out + (size_t)(r0 + 8) * DD + cb) = v;
            }
        }
    }
}

// ---------------- el/er ----------------
__global__ void node_attn(const float* __restrict__ h, const float* __restrict__ al,
                          const float* __restrict__ ar, float* __restrict__ el,
                          float* __restrict__ er) {
    int n = blockIdx.x;
    int head = threadIdx.x >> 5, lane = threadIdx.x & 31;
    float v = h[(size_t)n * DD + head * 32 + lane];
    float sl = v * al[head * 32 + lane];
    float sr = v * ar[head * 32 + lane];
    #pragma unroll
    for (int o = 16; o; o >>= 1) {
        sl += __shfl_down_sync(0xffffffffu, sl, o);
        sr += __shfl_down_sync(0xffffffffu, sr, o);
    }
    if (lane == 0) {
        el[n * HH + head] = sl;
        er[n * HH + head] = sr;
    }
}

// ---------------- zero accumulators ----------------
__global__ void zero_init(float* __restrict__ acc, float* __restrict__ z) {
    int i = blockIdx.x * blockDim.x + threadIdx.x;
    if (i < NN * DD) acc[i] = 0.f;
    if (i < NN * HH) z[i] = 0.f;
}

// ---------------- fused edge pass: z += exp(e); out[dst] += exp(e)*h[src] ----------------
__global__ void edge_fused(const int* __restrict__ src, const int* __restrict__ dst,
                           const float* __restrict__ el, const float* __restrict__ er,
                           float* __restrict__ z, const float* __restrict__ h,
                           float* __restrict__ out) {
    int gt = blockIdx.x * blockDim.x + threadIdx.x;
    int w = gt >> 5, lane = gt & 31;
    if (w >= ET) return;
    int s = (w < EE) ? __ldg(src + w) : (w - EE);
    int d = (w < EE) ? __ldg(dst + w) : (w - EE);
    float aexp = 0.f;
    if (lane < HH) {
        float e = leaky(__ldg(el + s * HH + lane) + __ldg(er + d * HH + lane));
        aexp = __expf(e);
        atomicAdd(&z[d * HH + lane], aexp);
    }
    float alpha = __shfl_sync(0xffffffffu, aexp, lane >> 2);
    const float4* hp = (const float4*)(h + (size_t)s * DD + lane * 8);
    float4 v0 = hp[0], v1 = hp[1];
    v0.x *= alpha; v0.y *= alpha; v0.z *= alpha; v0.w *= alpha;
    v1.x *= alpha; v1.y *= alpha; v1.z *= alpha; v1.w *= alpha;
    float* op = out + (size_t)d * DD + lane * 8;
    asm volatile("red.global.add.v4.f32 [%0], {%1,%2,%3,%4};"
                 :: "l"(op), "f"(v0.x), "f"(v0.y), "f"(v0.z), "f"(v0.w) : "memory");
    asm volatile("red.global.add.v4.f32 [%0], {%1,%2,%3,%4};"
                 :: "l"(op + 4), "f"(v1.x), "f"(v1.y), "f"(v1.z), "f"(v1.w) : "memory");
}

// ---------------- normalize + bias + leaky ----------------
__global__ void norm_bias_act(const float* __restrict__ in, const float* __restrict__ z,
                              const float* __restrict__ b, float* __restrict__ o) {
    int i = blockIdx.x * blockDim.x + threadIdx.x;   // float4 index
    if (i >= NN * DD / 4) return;
    int n = i >> 6, c4 = (i & 63) * 4;
    float zi = 1.f / z[n * HH + (c4 >> 5)];
    float4 v = ((const float4*)in)[i];
    const float4 bb = *(const float4*)(b + c4);
    v.x = leaky(v.x * zi + bb.x);
    v.y = leaky(v.y * zi + bb.y);
    v.z = leaky(v.z * zi + bb.z);
    v.w = leaky(v.w * zi + bb.w);
    ((float4*)o)[i] = v;
}

// ---------------- driver ----------------
extern "C" void kernel_launch(void* const* d_in, const int* in_sizes, int n_in,
                              void* d_out, int out_size) {
    const float* feats  = (const float*)d_in[0];
    const int*   src    = (const int*)d_in[1];
    const int*   dst    = (const int*)d_in[2];
    const float* proj_W = (const float*)d_in[3];
    const float* proj_b = (const float*)d_in[4];
    const float* Ws[2]  = { (const float*)d_in[5], (const float*)d_in[9] };
    const float* als[2] = { (const float*)d_in[6], (const float*)d_in[10] };
    const float* ars[2] = { (const float*)d_in[7], (const float*)d_in[11] };
    const float* bs[2]  = { (const float*)d_in[8], (const float*)d_in[12] };
    float* out = (float*)d_out;

    __nv_bfloat16 *Ab, *Bb;
    float *x, *h, *el, *er, *z;
    cudaGetSymbolAddress((void**)&Ab, g_A);
    cudaGetSymbolAddress((void**)&Bb, g_B);
    cudaGetSymbolAddress((void**)&x, g_x);
    cudaGetSymbolAddress((void**)&h, g_h);
    cudaGetSymbolAddress((void**)&el, g_el);
    cudaGetSymbolAddress((void**)&er, g_er);
    cudaGetSymbolAddress((void**)&z, g_z);

    cudaFuncSetAttribute(gemm_bf16x3, cudaFuncAttributeMaxDynamicSharedMemorySize, 2 * STG);

    int gACT = (NN * DD + 255) / 256;
    int gW = (DD * DD + 255) / 256;
    dim3 ggrid(DD / BN, NTILES);

    // proj: x = feats @ proj_W + proj_b
    split_act<<<gACT, 256>>>(feats, Ab);
    split_w<<<gW, 256>>>(proj_W, Bb);
    gemm_bf16x3<<<ggrid, 256, 2 * STG>>>(Ab, Bb, proj_b, x);

    for (int l = 0; l < 2; l++) {
        split_act<<<gACT, 256>>>(x, Ab);
        split_w<<<gW, 256>>>(Ws[l], Bb);
        gemm_bf16x3<<<ggrid, 256, 2 * STG>>>(Ab, Bb, nullptr, h);
        node_attn<<<NN, 256>>>(h, als[l], ars[l], el, er);
        zero_init<<<gACT, 256>>>(x, z);
        long tthreads = (long)ET * 32;
        edge_fused<<<(unsigned)((tthreads + 255) / 256), 256>>>(src, dst, el, er, z, h, x);
        norm_bias_act<<<(NN * DD / 4 + 255) / 256, 256>>>(x, z, bs[l], (l == 1) ? out : x);
    }
}

// round 4
// speedup vs baseline: 4.5087x; 2.1819x over previous
#include <cuda_runtime.h>
#include <cuda_bf16.h>
#include <cstdint>

#define NN 50000
#define EE 500000
#define ET (EE + NN)
#define DD 256
#define HH 8
#define NEGS 0.2f

#define KS 512                  // stored split-K: [0,256)=hi, [256,512)=lo
#define BM 128
#define BN 128
#define NCHUNK 12               // 3 passes x 4 chunks of K=64
#define NTILES ((NN + BM - 1) / BM)   // 391
#define MPAD (NTILES * BM)            // 50048
#define NB 196                  // scan blocks (ceil(NN/256))

// ---------------- scratch ----------------
__device__ __nv_bfloat16 g_A[(size_t)MPAD * KS];   // split activations (ping)
__device__ __nv_bfloat16 g_A2[(size_t)MPAD * KS];  // split activations (pong)
__device__ __nv_bfloat16 g_B[(size_t)DD * KS];     // split weight, B^T layout [n][k]
__device__ float g_h[NN * DD];
__device__ float g_el[NN * HH];
__device__ float g_er[NN * HH];
__device__ int g_cnt[NN + 256];
__device__ int g_bsum[256];
__device__ int g_bpre[256];
__device__ int g_off[NN + 1];
__device__ int g_cur[NN];
__device__ int g_csr[ET];

__device__ __forceinline__ float leaky(float v) { return v > 0.f ? v : NEGS * v; }
__device__ __forceinline__ uint32_t smem_u32(const void* p) {
    return (uint32_t)__cvta_generic_to_shared(p);
}

// ---------------- split kernels (vectorized fp32 -> bf16 hi/lo) ----------------
__global__ void split_act(const float* __restrict__ x, __nv_bfloat16* __restrict__ A) {
    int i = blockIdx.x * blockDim.x + threadIdx.x;     // float4 idx
    if (i >= NN * DD / 4) return;
    int m = i >> 6, c = (i & 63) * 4;
    float4 v = ((const float4*)x)[i];
    __nv_bfloat162 h0 = __floats2bfloat162_rn(v.x, v.y);
    __nv_bfloat162 h1 = __floats2bfloat162_rn(v.z, v.w);
    __nv_bfloat162 l0 = __floats2bfloat162_rn(v.x - __bfloat162float(h0.x),
                                              v.y - __bfloat162float(h0.y));
    __nv_bfloat162 l1 = __floats2bfloat162_rn(v.z - __bfloat162float(h1.x),
                                              v.w - __bfloat162float(h1.y));
    __nv_bfloat162* p = (__nv_bfloat162*)(A + (size_t)m * KS + c);
    p[0] = h0; p[1] = h1;
    __nv_bfloat162* q = (__nv_bfloat162*)(A + (size_t)m * KS + 256 + c);
    q[0] = l0; q[1] = l1;
}
__global__ void split_w(const float* __restrict__ W, __nv_bfloat16* __restrict__ Bm) {
    int i = blockIdx.x * blockDim.x + threadIdx.x;
    if (i >= DD * DD) return;
    int k = i >> 8, n = i & 255;           // W[k][n]
    float v = W[i];
    __nv_bfloat16 hi = __float2bfloat16(v);
    float lo = v - __bfloat162float(hi);
    Bm[(size_t)n * KS + k] = hi;
    Bm[(size_t)n * KS + 256 + k] = __float2bfloat16(lo);
}

// ---------------- CSR build ----------------
__global__ void csr_init(int* __restrict__ cnt) {
    int i = blockIdx.x * blockDim.x + threadIdx.x;
    if (i < NN) cnt[i] = 1;                 // self loop
}
__global__ void csr_hist(const int* __restrict__ dst, int* __restrict__ cnt) {
    int i = blockIdx.x * blockDim.x + threadIdx.x;
    if (i < EE) atomicAdd(&cnt[dst[i]], 1);
}
__global__ void csr_scan1(const int* __restrict__ cnt, int* __restrict__ bsum) {
    __shared__ int sd[256];
    int t = threadIdx.x, i = blockIdx.x * 256 + t;
    sd[t] = (i < NN) ? cnt[i] : 0;
    __syncthreads();
    for (int o = 128; o; o >>= 1) {
        if (t < o) sd[t] += sd[t + o];
        __syncthreads();
    }
    if (t == 0) bsum[blockIdx.x] = sd[0];
}
__global__ void csr_scan2(const int* __restrict__ bsum, int* __restrict__ bpre) {
    __shared__ int sd[256];
    int t = threadIdx.x;
    int v = (t < NB) ? bsum[t] : 0;
    sd[t] = v;
    __syncthreads();
    for (int o = 1; o < 256; o <<= 1) {
        int x = (t >= o) ? sd[t - o] : 0;
        __syncthreads();
        sd[t] += x;
        __syncthreads();
    }
    bpre[t] = sd[t] - v;                    // exclusive
}
__global__ void csr_scan3(const int* __restrict__ cnt, const int* __restrict__ bpre,
                          int* __restrict__ off, int* __restrict__ cur) {
    __shared__ int sd[256];
    int t = threadIdx.x, i = blockIdx.x * 256 + t;
    int v = (i < NN) ? cnt[i] : 0;
    sd[t] = v;
    __syncthreads();
    for (int o = 1; o < 256; o <<= 1) {
        int x = (t >= o) ? sd[t - o] : 0;
        __syncthreads();
        sd[t] += x;
        __syncthreads();
    }
    int ex = bpre[blockIdx.x] + sd[t] - v;
    if (i <= NN) {
        off[i] = ex;
        if (i < NN) cur[i] = ex;
    }
}
__global__ void csr_scatter(const int* __restrict__ src, const int* __restrict__ dst,
                            int* __restrict__ cur, int* __restrict__ csr) {
    int i = blockIdx.x * blockDim.x + threadIdx.x;
    if (i >= ET) return;
    int s = (i < EE) ? src[i] : (i - EE);
    int d = (i < EE) ? dst[i] : (i - EE);
    int pos = atomicAdd(&cur[d], 1);
    csr[pos] = s;
}

// ---------------- HMMA GEMM ----------------
#define STG 32768

__device__ __forceinline__ void fill_stage(const __nv_bfloat16* A, const __nv_bfloat16* B,
                                           uint32_t aB, uint32_t bB,
                                           int m0, int n0, int c, int tid) {
    int p = c >> 2, j = c & 3;
    int kA = ((p == 1) ? 256 : 0) + j * 64;
    int kB = ((p == 2) ? 256 : 0) + j * 64;
    const char* Ag = (const char*)(A + (size_t)m0 * KS + kA);
    const char* Bg = (const char*)(B + (size_t)n0 * KS + kB);
    #pragma unroll
    for (int i = 0; i < 4; i++) {
        int u = tid + i * 256;
        int r = u >> 3, s = u & 7;
        uint32_t off = (uint32_t)r * 128 + (uint32_t)((s ^ (r & 7)) << 4);
        unsigned long long sa = __cvta_generic_to_global(Ag + (size_t)r * 1024 + s * 16);
        unsigned long long sbg = __cvta_generic_to_global(Bg + (size_t)r * 1024 + s * 16);
        asm volatile("cp.async.cg.shared.global [%0], [%1], 16;" :: "r"(aB + off), "l"(sa));
        asm volatile("cp.async.cg.shared.global [%0], [%1], 16;" :: "r"(bB + off), "l"(sbg));
    }
}

__device__ __forceinline__ void mma16816(float* d, const uint32_t* a, const uint32_t* b) {
    asm volatile("mma.sync.aligned.m16n8k16.row.col.f32.bf16.bf16.f32 "
                 "{%0,%1,%2,%3}, {%4,%5,%6,%7}, {%8,%9}, {%0,%1,%2,%3};"
                 : "+f"(d[0]), "+f"(d[1]), "+f"(d[2]), "+f"(d[3])
                 : "r"(a[0]), "r"(a[1]), "r"(a[2]), "r"(a[3]), "r"(b[0]), "r"(b[1]));
}

__global__ void __launch_bounds__(256)
gemm_bf16x3(const __nv_bfloat16* __restrict__ A, const __nv_bfloat16* __restrict__ B,
            const float* __restrict__ bias, float* __restrict__ outf,
            __nv_bfloat16* __restrict__ outA,
            const float* __restrict__ al, const float* __restrict__ ar,
            float* __restrict__ el, float* __restrict__ er) {
    extern __shared__ char smem[];
    uint32_t sb = smem_u32(smem);
    int tid = threadIdx.x, wid = tid >> 5, lane = tid & 31;
    int m0 = blockIdx.y * BM, n0 = blockIdx.x * BN;
    int warp_m = (wid & 3) * 32, warp_n = (wid >> 2) * 64;

    float acc[2][8][4];
    #pragma unroll
    for (int mt = 0; mt < 2; mt++)
        #pragma unroll
        for (int nt = 0; nt < 8; nt++)
            #pragma unroll
            for (int q = 0; q < 4; q++) acc[mt][nt][q] = 0.f;

    fill_stage(A, B, sb, sb + 16384, m0, n0, 0, tid);
    asm volatile("cp.async.commit_group;" ::: "memory");

    for (int c = 0; c < NCHUNK; c++) {
        if (c + 1 < NCHUNK) {
            uint32_t st = ((c + 1) & 1) * STG;
            fill_stage(A, B, sb + st, sb + st + 16384, m0, n0, c + 1, tid);
            asm volatile("cp.async.commit_group;" ::: "memory");
            asm volatile("cp.async.wait_group 1;" ::: "memory");
        } else {
            asm volatile("cp.async.wait_group 0;" ::: "memory");
        }
        __syncthreads();
        uint32_t as = sb + (c & 1) * STG;
        uint32_t bs = as + 16384;
        #pragma unroll
        for (int kk = 0; kk < 4; kk++) {
            uint32_t a[2][4], b[8][2];
            {
                int rr = lane & 15, half = lane >> 4;
                int s = kk * 2 + half;
                #pragma unroll
                for (int mt = 0; mt < 2; mt++) {
                    int row = warp_m + mt * 16 + rr;
                    uint32_t ad = as + (uint32_t)row * 128 + (uint32_t)((s ^ (row & 7)) << 4);
                    asm volatile("ldmatrix.sync.aligned.m8n8.x4.shared.b16 {%0,%1,%2,%3}, [%4];"
                                 : "=r"(a[mt][0]), "=r"(a[mt][1]), "=r"(a[mt][2]), "=r"(a[mt][3])
                                 : "r"(ad));
                }
            }
            {
                int half = (lane >> 3) & 1;
                int s = kk * 2 + half;
                int nro = ((lane >> 4) << 3) + (lane & 7);
                #pragma unroll
                for (int j = 0; j < 4; j++) {
                    int row = warp_n + j * 16 + nro;
                    uint32_t bd = bs + (uint32_t)row * 128 + (uint32_t)((s ^ (row & 7)) << 4);
                    asm volatile("ldmatrix.sync.aligned.m8n8.x4.shared.b16 {%0,%1,%2,%3}, [%4];"
                                 : "=r"(b[2*j][0]), "=r"(b[2*j][1]), "=r"(b[2*j+1][0]), "=r"(b[2*j+1][1])
                                 : "r"(bd));
                }
            }
            #pragma unroll
            for (int mt = 0; mt < 2; mt++)
                #pragma unroll
                for (int nt = 0; nt < 8; nt++)
                    mma16816(acc[mt][nt], a[mt], b[nt]);
        }
        __syncthreads();
    }

    // ---------------- epilogue ----------------
    int rin = lane >> 2, colq = (lane & 3) * 2;
    #pragma unroll
    for (int mt = 0; mt < 2; mt++) {
        int r0 = m0 + warp_m + mt * 16 + rin;
        #pragma unroll
        for (int nt = 0; nt < 8; nt++) {
            int cb = n0 + warp_n + nt * 8 + colq;
            float b0 = bias ? bias[cb] : 0.f, b1 = bias ? bias[cb + 1] : 0.f;
            float v0 = acc[mt][nt][0] + b0, v1 = acc[mt][nt][1] + b1;
            float v2 = acc[mt][nt][2] + b0, v3 = acc[mt][nt][3] + b1;
            if (outf) {
                if (r0 < NN) *(float2*)(outf + (size_t)r0 * DD + cb) = make_float2(v0, v1);
                if (r0 + 8 < NN) *(float2*)(outf + (size_t)(r0 + 8) * DD + cb) = make_float2(v2, v3);
            }
            if (outA) {
                if (r0 < NN) {
                    __nv_bfloat162 hi = __floats2bfloat162_rn(v0, v1);
                    __nv_bfloat162 lo = __floats2bfloat162_rn(v0 - __bfloat162float(hi.x),
                                                              v1 - __bfloat162float(hi.y));
                    *(__nv_bfloat162*)(outA + (size_t)r0 * KS + cb) = hi;
                    *(__nv_bfloat162*)(outA + (size_t)r0 * KS + 256 + cb) = lo;
                }
                if (r0 + 8 < NN) {
                    __nv_bfloat162 hi = __floats2bfloat162_rn(v2, v3);
                    __nv_bfloat162 lo = __floats2bfloat162_rn(v2 - __bfloat162float(hi.x),
                                                              v3 - __bfloat162float(hi.y));
                    *(__nv_bfloat162*)(outA + (size_t)(r0 + 8) * KS + cb) = hi;
                    *(__nv_bfloat162*)(outA + (size_t)(r0 + 8) * KS + 256 + cb) = lo;
                }
            }
        }
        if (el) {
            // warp covers 2 heads (32 cols each); reduce over 4 colq-lanes sharing rin
            #pragma unroll
            for (int hh2 = 0; hh2 < 2; hh2++) {
                int ghead = (n0 + warp_n + hh2 * 32) >> 5;
                float sl0 = 0.f, sr0 = 0.f, sl1 = 0.f, sr1 = 0.f;
                #pragma unroll
                for (int t = 0; t < 4; t++) {
                    int nt = hh2 * 4 + t;
                    int cg = n0 + warp_n + nt * 8 + colq;
                    float w0 = __ldg(al + cg), w1 = __ldg(al + cg + 1);
                    float u0 = __ldg(ar + cg), u1 = __ldg(ar + cg + 1);
                    sl0 += acc[mt][nt][0] * w0 + acc[mt][nt][1] * w1;
                    sr0 += acc[mt][nt][0] * u0 + acc[mt][nt][1] * u1;
                    sl1 += acc[mt][nt][2] * w0 + acc[mt][nt][3] * w1;
                    sr1 += acc[mt][nt][2] * u0 + acc[mt][nt][3] * u1;
                }
                #pragma unroll
                for (int o = 1; o < 4; o <<= 1) {
                    sl0 += __shfl_xor_sync(0xffffffffu, sl0, o);
                    sr0 += __shfl_xor_sync(0xffffffffu, sr0, o);
                    sl1 += __shfl_xor_sync(0xffffffffu, sl1, o);
                    sr1 += __shfl_xor_sync(0xffffffffu, sr1, o);
                }
                if (colq == 0) {
                    if (r0 < NN) { el[r0 * HH + ghead] = sl0; er[r0 * HH + ghead] = sr0; }
                    if (r0 + 8 < NN) { el[(r0 + 8) * HH + ghead] = sl1; er[(r0 + 8) * HH + ghead] = sr1; }
                }
            }
        }
    }
}

// ---------------- CSR aggregation: block per dst node, 64 threads ----------------
__global__ void __launch_bounds__(64)
agg_node(const int* __restrict__ off, const int* __restrict__ csr,
         const float* __restrict__ el, const float* __restrict__ er,
         const float* __restrict__ h, const float* __restrict__ bias,
         float* __restrict__ outf, __nv_bfloat16* __restrict__ outA) {
    int d = blockIdx.x;
    int tid = threadIdx.x, w = tid >> 5, lane = tid & 31;
    int beg = __ldg(off + d), end = __ldg(off + d + 1);
    int hloc = lane >> 3;                        // 0..3 within warp
    float erv = (lane < 4) ? __ldg(er + d * HH + w * 4 + lane) : 0.f;
    float4 acc = make_float4(0.f, 0.f, 0.f, 0.f);
    float zacc = 0.f;
    for (int j = beg; j < end; j++) {
        int s = __ldg(csr + j);
        float aexp = 0.f;
        if (lane < 4) {
            float e = __ldg(el + s * HH + w * 4 + lane) + erv;
            aexp = __expf(leaky(e));
            zacc += aexp;
        }
        float alpha = __shfl_sync(0xffffffffu, aexp, hloc);
        float4 v = *(const float4*)(h + (size_t)s * DD + w * 128 + lane * 4);
        acc.x += alpha * v.x; acc.y += alpha * v.y;
        acc.z += alpha * v.z; acc.w += alpha * v.w;
    }
    float zinv = (lane < 4) ? (1.f / zacc) : 0.f;
    float zv = __shfl_sync(0xffffffffu, zinv, hloc);
    int c = w * 128 + lane * 4;
    const float4 bb = *(const float4*)(bias + c);
    float r0 = leaky(acc.x * zv + bb.x);
    float r1 = leaky(acc.y * zv + bb.y);
    float r2 = leaky(acc.z * zv + bb.z);
    float r3 = leaky(acc.w * zv + bb.w);
    if (outf) {
        *(float4*)(outf + (size_t)d * DD + c) = make_float4(r0, r1, r2, r3);
    } else {
        __nv_bfloat162 h0 = __floats2bfloat162_rn(r0, r1);
        __nv_bfloat162 h1 = __floats2bfloat162_rn(r2, r3);
        __nv_bfloat162 l0 = __floats2bfloat162_rn(r0 - __bfloat162float(h0.x),
                                                  r1 - __bfloat162float(h0.y));
        __nv_bfloat162 l1 = __floats2bfloat162_rn(r2 - __bfloat162float(h1.x),
                                                  r3 - __bfloat162float(h1.y));
        __nv_bfloat162* p = (__nv_bfloat162*)(outA + (size_t)d * KS + c);
        p[0] = h0; p[1] = h1;
        __nv_bfloat162* q = (__nv_bfloat162*)(outA + (size_t)d * KS + 256 + c);
        q[0] = l0; q[1] = l1;
    }
}

// ---------------- driver ----------------
extern "C" void kernel_launch(void* const* d_in, const int* in_sizes, int n_in,
                              void* d_out, int out_size) {
    const float* feats  = (const float*)d_in[0];
    const int*   src    = (const int*)d_in[1];
    const int*   dst    = (const int*)d_in[2];
    const float* proj_W = (const float*)d_in[3];
    const float* proj_b = (const float*)d_in[4];
    const float* Ws[2]  = { (const float*)d_in[5], (const float*)d_in[9] };
    const float* als[2] = { (const float*)d_in[6], (const float*)d_in[10] };
    const float* ars[2] = { (const float*)d_in[7], (const float*)d_in[11] };
    const float* bs[2]  = { (const float*)d_in[8], (const float*)d_in[12] };
    float* out = (float*)d_out;

    __nv_bfloat16 *Ab, *A2b, *Bb;
    float *h, *el, *er;
    int *cnt, *bsum, *bpre, *off, *cur, *csr;
    cudaGetSymbolAddress((void**)&Ab, g_A);
    cudaGetSymbolAddress((void**)&A2b, g_A2);
    cudaGetSymbolAddress((void**)&Bb, g_B);
    cudaGetSymbolAddress((void**)&h, g_h);
    cudaGetSymbolAddress((void**)&el, g_el);
    cudaGetSymbolAddress((void**)&er, g_er);
    cudaGetSymbolAddress((void**)&cnt, g_cnt);
    cudaGetSymbolAddress((void**)&bsum, g_bsum);
    cudaGetSymbolAddress((void**)&bpre, g_bpre);
    cudaGetSymbolAddress((void**)&off, g_off);
    cudaGetSymbolAddress((void**)&cur, g_cur);
    cudaGetSymbolAddress((void**)&csr, g_csr);

    cudaFuncSetAttribute(gemm_bf16x3, cudaFuncAttributeMaxDynamicSharedMemorySize, 2 * STG);

    dim3 ggrid(DD / BN, NTILES);
    int gW = (DD * DD + 255) / 256;

    // CSR build (graph is static per call set; rebuilt every call deterministically)
    csr_init<<<(NN + 255) / 256, 256>>>(cnt);
    csr_hist<<<(EE + 255) / 256, 256>>>(dst, cnt);
    csr_scan1<<<NB, 256>>>(cnt, bsum);
    csr_scan2<<<1, 256>>>(bsum, bpre);
    csr_scan3<<<NB, 256>>>(cnt, bpre, off, cur);
    csr_scatter<<<(ET + 255) / 256, 256>>>(src, dst, cur, csr);

    // proj: A(feats) -> split x into A2
    split_act<<<(NN * DD / 4 + 255) / 256, 256>>>(feats, Ab);
    split_w<<<gW, 256>>>(proj_W, Bb);
    gemm_bf16x3<<<ggrid, 256, 2 * STG>>>(Ab, Bb, proj_b, nullptr, A2b,
                                         nullptr, nullptr, nullptr, nullptr);

    for (int l = 0; l < 2; l++) {
        split_w<<<gW, 256>>>(Ws[l], Bb);
        const __nv_bfloat16* Asrc = (l == 0) ? A2b : Ab;
        gemm_bf16x3<<<ggrid, 256, 2 * STG>>>(Asrc, Bb, nullptr, h, nullptr,
                                             als[l], ars[l], el, er);
        agg_node<<<NN, 64>>>(off, csr, el, er, h, bs[l],
                             (l == 1) ? out : nullptr, (l == 0) ? Ab : nullptr);
    }
}